// round 1
// baseline (speedup 1.0000x reference)
#include <cuda_runtime.h>
#include <math.h>

#define Bn 4096
#define DF 128
#define NC 512
#define TILE 128
#define TPB 256
#define KCH 32          // K-chunk
#define STA 132         // smem tile stride (pad)
#define STT 129         // transpose stage stride (pad)

// scratch (device globals; no allocation allowed)
__device__ double g_acc[8];                 // sw1,swd1, sw2,swd2, sw3,swd3, ps,pss
__device__ unsigned long long g_cnt[4];     // counts for mask.any()
__device__ float g_sq[Bn];

// ---------------------------------------------------------------------------
// prep: zero accumulators + per-row squared norms
// ---------------------------------------------------------------------------
__global__ void __launch_bounds__(TPB) prep_kernel(const float* __restrict__ x) {
    if (blockIdx.x == 0 && threadIdx.x < 12) {
        if (threadIdx.x < 8) g_acc[threadIdx.x] = 0.0;
        else                 g_cnt[threadIdx.x - 8] = 0ull;
    }
    int row  = blockIdx.x * (TPB / 32) + (threadIdx.x >> 5);
    int lane = threadIdx.x & 31;
    const float* xr = x + (size_t)row * DF;
    float s = 0.f;
#pragma unroll
    for (int k = 0; k < DF; k += 32) {
        float v = xr[k + lane];
        s = fmaf(v, v, s);
    }
#pragma unroll
    for (int o = 16; o; o >>= 1) s += __shfl_xor_sync(0xffffffffu, s, o);
    if (lane == 0) g_sq[row] = s;
}

__device__ __forceinline__ double wredd(double v) {
#pragma unroll
    for (int o = 16; o; o >>= 1) v += __shfl_xor_sync(0xffffffffu, v, o);
    return v;
}
__device__ __forceinline__ unsigned wredu(unsigned v) {
#pragma unroll
    for (int o = 16; o; o >>= 1) v += __shfl_xor_sync(0xffffffffu, v, o);
    return v;
}

// ---------------------------------------------------------------------------
// fused: dist tile GEMM (upper-tri only, mirrored) + loss accumulation
// ---------------------------------------------------------------------------
__global__ void __launch_bounds__(TPB, 2)
dist_loss_kernel(const float* __restrict__ x, const int* __restrict__ y,
                 const float* __restrict__ mean, const float* __restrict__ stdv,
                 const float* __restrict__ noise, float* __restrict__ out)
{
    const int bi = blockIdx.y, bj = blockIdx.x;
    if (bj < bi) return;                       // lower tiles produced by mirror
    const int i0 = bi * TILE, j0 = bj * TILE;

    __shared__ float sm[2 * KCH * STA];        // 33.8 KB; reused as transpose stage
    float* As = sm;
    float* Bs = sm + KCH * STA;

    const int tid = threadIdx.x;
    const int tx = tid & 15, ty = tid >> 4;
    const int ia = ty * 8, ja = tx * 8;

    float acc[8][8];
#pragma unroll
    for (int a = 0; a < 8; a++)
#pragma unroll
        for (int b = 0; b < 8; b++) acc[a][b] = 0.f;

    for (int c = 0; c < DF / KCH; c++) {
        __syncthreads();
#pragma unroll
        for (int t = 0; t < (TILE * KCH) / TPB; t++) {
            int idx = tid + t * TPB;           // 0..4095
            int r = idx >> 5, kk = idx & 31;
            As[kk * STA + r] = x[(size_t)(i0 + r) * DF + c * KCH + kk];
            Bs[kk * STA + r] = x[(size_t)(j0 + r) * DF + c * KCH + kk];
        }
        __syncthreads();
#pragma unroll
        for (int k = 0; k < KCH; k++) {
            float4 a0 = *(const float4*)&As[k * STA + ia];
            float4 a1 = *(const float4*)&As[k * STA + ia + 4];
            float4 b0 = *(const float4*)&Bs[k * STA + ja];
            float4 b1 = *(const float4*)&Bs[k * STA + ja + 4];
            float av[8] = {a0.x, a0.y, a0.z, a0.w, a1.x, a1.y, a1.z, a1.w};
            float bv[8] = {b0.x, b0.y, b0.z, b0.w, b1.x, b1.y, b1.z, b1.w};
#pragma unroll
            for (int a = 0; a < 8; a++)
#pragma unroll
                for (int b = 0; b < 8; b++)
                    acc[a][b] = fmaf(av[a], bv[b], acc[a][b]);
        }
    }

    float sqi[8], sqj[8];
    int yi[8], yj[8];
#pragma unroll
    for (int a = 0; a < 8; a++) {
        sqi[a] = g_sq[i0 + ia + a];
        sqj[a] = g_sq[j0 + ja + a];
        yi[a]  = y[i0 + ia + a];
        yj[a]  = y[j0 + ja + a];
    }

    // dist in-place; coalesced store of the (i,j) tile
#pragma unroll
    for (int a = 0; a < 8; a++) {
#pragma unroll
        for (int b = 0; b < 8; b++)
            acc[a][b] = sqi[a] + sqj[b] - 2.f * acc[a][b];
        float4* op = (float4*)&out[(size_t)(i0 + ia + a) * Bn + j0 + ja];
        op[0] = make_float4(acc[a][0], acc[a][1], acc[a][2], acc[a][3]);
        op[1] = make_float4(acc[a][4], acc[a][5], acc[a][6], acc[a][7]);
    }

    // ---- loss accumulation (strict upper triangle only) ----
    double p0 = 0, p1 = 0, p2 = 0, p3 = 0, p4 = 0, p5 = 0, p6 = 0, p7 = 0;
    unsigned c0 = 0, c1 = 0, c2 = 0, c3 = 0;

#pragma unroll
    for (int a = 0; a < 8; a++) {
        const int i = i0 + ia + a;
        if (j0 + ja + 7 <= i) continue;        // no j>i in this thread-row
        const float4 n0 = *(const float4*)&noise[(size_t)i * Bn + j0 + ja];
        const float4 n1 = *(const float4*)&noise[(size_t)i * Bn + j0 + ja + 4];
        float nv[8] = {n0.x, n0.y, n0.z, n0.w, n1.x, n1.y, n1.z, n1.w};
        const float* mrow = mean + (size_t)yi[a] * NC;
        const float* srow = stdv + (size_t)yi[a] * NC;
        const int gi = i >> 3;
#pragma unroll
        for (int b = 0; b < 8; b++) {
            const int j = j0 + ja + b;
            if (j <= i) continue;
            const float cm  = __ldg(&mrow[yj[b]]);
            const float cs  = __ldg(&srow[yj[b]]);
            const float obs = fmaf(cs, nv[b], cm);
            const float d   = acc[a][b];
            if ((j >> 3) != gi) {              // negative pair
                const float tn1  = obs - 2.5f * cs;
                const float tmid = obs - 1.5f * cs;
                if (d < tn1) {
                    double w = exp(10.0 * (double)(tn1 - d));
                    p0 += w; p1 += w * (double)d; c0++;
                } else if (d > tn1 && d < tmid) {
                    double w = exp(5.0 * (double)(tmid - d));
                    p2 += w; p3 += w * (double)d; c1++;
                } else {
                    const float thi = obs + 1.5f * cs;
                    if (d > tmid && d < thi) {
                        double w = exp(5.0 * (double)(thi - d));
                        p4 += w; p5 += w * (double)d; c2++;
                    }
                }
            } else {                           // positive pair
                const float tp = obs + 2.0f * cs;
                if (d > tp) { p6 += (double)d; p7 += (double)d * (double)d; c3++; }
            }
        }
    }

    p0 = wredd(p0); p1 = wredd(p1); p2 = wredd(p2); p3 = wredd(p3);
    p4 = wredd(p4); p5 = wredd(p5); p6 = wredd(p6); p7 = wredd(p7);
    c0 = wredu(c0); c1 = wredu(c1); c2 = wredu(c2); c3 = wredu(c3);
    if ((tid & 31) == 0) {
        atomicAdd(&g_acc[0], p0); atomicAdd(&g_acc[1], p1);
        atomicAdd(&g_acc[2], p2); atomicAdd(&g_acc[3], p3);
        atomicAdd(&g_acc[4], p4); atomicAdd(&g_acc[5], p5);
        atomicAdd(&g_acc[6], p6); atomicAdd(&g_acc[7], p7);
        atomicAdd(&g_cnt[0], (unsigned long long)c0);
        atomicAdd(&g_cnt[1], (unsigned long long)c1);
        atomicAdd(&g_cnt[2], (unsigned long long)c2);
        atomicAdd(&g_cnt[3], (unsigned long long)c3);
    }

    // ---- mirror tile (j0,i0) via smem transpose, two 64-col halves ----
    if (bj > bi) {
        float* Ts = sm;                        // [64][STT] stage
#pragma unroll
        for (int h = 0; h < 2; h++) {
            __syncthreads();
            if ((tx >> 3) == h) {
                const int jloc = ja - 64 * h;  // 0..56
#pragma unroll
                for (int b = 0; b < 8; b++)
#pragma unroll
                    for (int a = 0; a < 8; a++)
                        Ts[(jloc + b) * STT + (ia + a)] = acc[a][b];
            }
            __syncthreads();
#pragma unroll
            for (int t = 0; t < (64 * TILE) / (TPB * 4); t++) {
                int idx = tid + t * TPB;       // 0..2047 (float4 units)
                int jr = idx >> 5, ic4 = (idx & 31) << 2;
                float4 v = make_float4(Ts[jr * STT + ic4],     Ts[jr * STT + ic4 + 1],
                                       Ts[jr * STT + ic4 + 2], Ts[jr * STT + ic4 + 3]);
                *(float4*)&out[(size_t)(j0 + 64 * h + jr) * Bn + i0 + ic4] = v;
            }
        }
    }
}

// ---------------------------------------------------------------------------
// finalize: assemble scalar loss
// ---------------------------------------------------------------------------
__global__ void finalize_kernel(float* __restrict__ out) {
    double l1 = g_cnt[0] ? -(g_acc[1] / (g_acc[0] > 0.0 ? g_acc[0] : 1.0)) : -0.0001;
    double l2 = g_cnt[1] ? -(g_acc[3] / (g_acc[2] > 0.0 ? g_acc[2] : 1.0)) : -0.0001;
    double l3 = g_cnt[2] ? -(g_acc[5] / (g_acc[4] > 0.0 ? g_acc[4] : 1.0)) : -0.0001;
    double lp = g_cnt[3] ?  (g_acc[7] / (g_acc[6] != 0.0 ? g_acc[6] : 1.0)) :  0.0001;
    out[(size_t)Bn * Bn] = (float)(1.0 + (l1 + l2 + l3 + lp) * 0.25);
}

extern "C" void kernel_launch(void* const* d_in, const int* in_sizes, int n_in,
                              void* d_out, int out_size) {
    const float* x     = (const float*)d_in[0];
    const int*   y     = (const int*)d_in[1];
    const float* mean  = (const float*)d_in[2];
    const float* stdv  = (const float*)d_in[3];
    const float* noise = (const float*)d_in[4];
    float* out = (float*)d_out;

    prep_kernel<<<Bn / (TPB / 32), TPB>>>(x);
    dim3 grid(Bn / TILE, Bn / TILE);
    dist_loss_kernel<<<grid, TPB>>>(x, y, mean, stdv, noise, out);
    finalize_kernel<<<1, 1>>>(out);
}

// round 2
// speedup vs baseline: 3.0127x; 3.0127x over previous
#include <cuda_runtime.h>
#include <math.h>

#define Bn 4096
#define DF 128
#define NC 512
#define TILE 128
#define TPB 256
#define KCH 32          // K-chunk
#define STA 132         // smem tile stride (pad)
#define STT 129         // transpose stage stride (pad)

// scratch (device globals; no allocation allowed)
__device__ double g_acc[8];                 // sw1,swd1, sw2,swd2, sw3,swd3, ps,pss
__device__ unsigned long long g_cnt[4];     // counts for mask.any()
__device__ float g_sq[Bn];

// ---------------------------------------------------------------------------
// prep: zero accumulators + per-row squared norms
// ---------------------------------------------------------------------------
__global__ void __launch_bounds__(TPB) prep_kernel(const float* __restrict__ x) {
    if (blockIdx.x == 0 && threadIdx.x < 12) {
        if (threadIdx.x < 8) g_acc[threadIdx.x] = 0.0;
        else                 g_cnt[threadIdx.x - 8] = 0ull;
    }
    int row  = blockIdx.x * (TPB / 32) + (threadIdx.x >> 5);
    int lane = threadIdx.x & 31;
    const float* xr = x + (size_t)row * DF;
    float s = 0.f;
#pragma unroll
    for (int k = 0; k < DF; k += 32) {
        float v = xr[k + lane];
        s = fmaf(v, v, s);
    }
#pragma unroll
    for (int o = 16; o; o >>= 1) s += __shfl_xor_sync(0xffffffffu, s, o);
    if (lane == 0) g_sq[row] = s;
}

__device__ __forceinline__ double wredd(double v) {
#pragma unroll
    for (int o = 16; o; o >>= 1) v += __shfl_xor_sync(0xffffffffu, v, o);
    return v;
}
__device__ __forceinline__ unsigned wredu(unsigned v) {
#pragma unroll
    for (int o = 16; o; o >>= 1) v += __shfl_xor_sync(0xffffffffu, v, o);
    return v;
}

// exp(logit) with logit in [0, ~220]: exp2 split, fp32 mantissa, double scale.
__device__ __forceinline__ double fast_exp_pos(float logit) {
    float arg = logit * 1.4426950408889634f;   // log2(e)
    float fi  = floorf(arg);
    float fr  = arg - fi;
    long long e = (long long)(1023 + (int)fi) << 52;
    return __longlong_as_double(e) * (double)exp2f(fr);
}

// ---------------------------------------------------------------------------
// fused: dist tile GEMM (upper-tri only, mirrored) + loss accumulation
// ---------------------------------------------------------------------------
__global__ void __launch_bounds__(TPB, 1)
dist_loss_kernel(const float* __restrict__ x, const int* __restrict__ y,
                 const float* __restrict__ mean, const float* __restrict__ stdv,
                 const float* __restrict__ noise, float* __restrict__ out)
{
    const int bi = blockIdx.y, bj = blockIdx.x;
    if (bj < bi) return;                       // lower tiles produced by mirror
    const int i0 = bi * TILE, j0 = bj * TILE;

    __shared__ float sm[2 * KCH * STA];        // 33.8 KB; reused as transpose stage
    __shared__ double sred[8][8];              // block reduction: [warp][acc]
    __shared__ unsigned scnt[8][4];
    float* As = sm;
    float* Bs = sm + KCH * STA;

    const int tid = threadIdx.x;
    const int tx = tid & 15, ty = tid >> 4;
    const int ia = ty * 8, ja = tx * 8;

    float acc[8][8];
#pragma unroll
    for (int a = 0; a < 8; a++)
#pragma unroll
        for (int b = 0; b < 8; b++) acc[a][b] = 0.f;

    for (int c = 0; c < DF / KCH; c++) {
        __syncthreads();
#pragma unroll
        for (int t = 0; t < (TILE * KCH) / TPB; t++) {
            int idx = tid + t * TPB;           // 0..4095
            int r = idx >> 5, kk = idx & 31;
            As[kk * STA + r] = x[(size_t)(i0 + r) * DF + c * KCH + kk];
            Bs[kk * STA + r] = x[(size_t)(j0 + r) * DF + c * KCH + kk];
        }
        __syncthreads();
#pragma unroll
        for (int k = 0; k < KCH; k++) {
            float4 a0 = *(const float4*)&As[k * STA + ia];
            float4 a1 = *(const float4*)&As[k * STA + ia + 4];
            float4 b0 = *(const float4*)&Bs[k * STA + ja];
            float4 b1 = *(const float4*)&Bs[k * STA + ja + 4];
            float av[8] = {a0.x, a0.y, a0.z, a0.w, a1.x, a1.y, a1.z, a1.w};
            float bv[8] = {b0.x, b0.y, b0.z, b0.w, b1.x, b1.y, b1.z, b1.w};
#pragma unroll
            for (int a = 0; a < 8; a++)
#pragma unroll
                for (int b = 0; b < 8; b++)
                    acc[a][b] = fmaf(av[a], bv[b], acc[a][b]);
        }
    }

    float sqi[8], sqj[8];
    int yi[8], yj[8];
#pragma unroll
    for (int a = 0; a < 8; a++) {
        sqi[a] = g_sq[i0 + ia + a];
        sqj[a] = g_sq[j0 + ja + a];
        yi[a]  = y[i0 + ia + a];
        yj[a]  = y[j0 + ja + a];
    }

    // dist in-place; coalesced store of the (i,j) tile
#pragma unroll
    for (int a = 0; a < 8; a++) {
#pragma unroll
        for (int b = 0; b < 8; b++)
            acc[a][b] = sqi[a] + sqj[b] - 2.f * acc[a][b];
        float4* op = (float4*)&out[(size_t)(i0 + ia + a) * Bn + j0 + ja];
        op[0] = make_float4(acc[a][0], acc[a][1], acc[a][2], acc[a][3]);
        op[1] = make_float4(acc[a][4], acc[a][5], acc[a][6], acc[a][7]);
    }

    // ---- loss accumulation (strict upper triangle only) ----
    double p[8] = {0, 0, 0, 0, 0, 0, 0, 0};
    unsigned cc[4] = {0, 0, 0, 0};

#pragma unroll
    for (int a = 0; a < 8; a++) {
        const int i = i0 + ia + a;
        if (j0 + ja + 7 <= i) continue;        // no j>i in this thread-row
        const float4 n0 = *(const float4*)&noise[(size_t)i * Bn + j0 + ja];
        const float4 n1 = *(const float4*)&noise[(size_t)i * Bn + j0 + ja + 4];
        float nv[8] = {n0.x, n0.y, n0.z, n0.w, n1.x, n1.y, n1.z, n1.w};
        const float* mrow = mean + (size_t)yi[a] * NC;
        const float* srow = stdv + (size_t)yi[a] * NC;
        const int gi = i >> 3;
#pragma unroll
        for (int b = 0; b < 8; b++) {
            const int j = j0 + ja + b;
            if (j <= i) continue;
            const float cm  = __ldg(&mrow[yj[b]]);
            const float cs  = __ldg(&srow[yj[b]]);
            const float obs = fmaf(cs, nv[b], cm);
            const float d   = acc[a][b];
            if ((j >> 3) != gi) {              // negative pair
                const float tn1  = obs - 2.5f * cs;
                const float tmid = obs - 1.5f * cs;
                if (d < tn1) {
                    double w = fast_exp_pos(10.f * (tn1 - d));
                    p[0] += w; p[1] += w * (double)d; cc[0]++;
                } else if (d > tn1 && d < tmid) {
                    double w = fast_exp_pos(5.f * (tmid - d));
                    p[2] += w; p[3] += w * (double)d; cc[1]++;
                } else {
                    const float thi = obs + 1.5f * cs;
                    if (d > tmid && d < thi) {
                        double w = fast_exp_pos(5.f * (thi - d));
                        p[4] += w; p[5] += w * (double)d; cc[2]++;
                    }
                }
            } else {                           // positive pair
                const float tp = obs + 2.0f * cs;
                if (d > tp) { p[6] += (double)d; p[7] += (double)d * (double)d; cc[3]++; }
            }
        }
    }

#pragma unroll
    for (int q = 0; q < 8; q++) p[q] = wredd(p[q]);
#pragma unroll
    for (int q = 0; q < 4; q++) cc[q] = wredu(cc[q]);

    const int warp = tid >> 5;
    if ((tid & 31) == 0) {
#pragma unroll
        for (int q = 0; q < 8; q++) sred[warp][q] = p[q];
#pragma unroll
        for (int q = 0; q < 4; q++) scnt[warp][q] = cc[q];
    }
    __syncthreads();
    if (tid < 8) {                             // one thread per accumulator
        double s = 0;
#pragma unroll
        for (int w = 0; w < 8; w++) s += sred[w][tid];
        if (s != 0.0) atomicAdd(&g_acc[tid], s);
    } else if (tid < 12) {
        unsigned long long s = 0;
#pragma unroll
        for (int w = 0; w < 8; w++) s += scnt[w][tid - 8];
        if (s) atomicAdd(&g_cnt[tid - 8], s);
    }

    // ---- mirror tile (j0,i0) via smem transpose, two 64-col halves ----
    if (bj > bi) {
        float* Ts = sm;                        // [64][STT] stage
#pragma unroll
        for (int h = 0; h < 2; h++) {
            __syncthreads();
            if ((tx >> 3) == h) {
                const int jloc = ja - 64 * h;  // 0..56
#pragma unroll
                for (int b = 0; b < 8; b++)
#pragma unroll
                    for (int a = 0; a < 8; a++)
                        Ts[(jloc + b) * STT + (ia + a)] = acc[a][b];
            }
            __syncthreads();
#pragma unroll
            for (int t = 0; t < (64 * TILE) / (TPB * 4); t++) {
                int idx = tid + t * TPB;       // 0..2047 (float4 units)
                int jr = idx >> 5, ic4 = (idx & 31) << 2;
                float4 v = make_float4(Ts[jr * STT + ic4],     Ts[jr * STT + ic4 + 1],
                                       Ts[jr * STT + ic4 + 2], Ts[jr * STT + ic4 + 3]);
                *(float4*)&out[(size_t)(j0 + 64 * h + jr) * Bn + i0 + ic4] = v;
            }
        }
    }
}

// ---------------------------------------------------------------------------
// finalize: assemble scalar loss
// ---------------------------------------------------------------------------
__global__ void finalize_kernel(float* __restrict__ out) {
    double l1 = g_cnt[0] ? -(g_acc[1] / (g_acc[0] > 0.0 ? g_acc[0] : 1.0)) : -0.0001;
    double l2 = g_cnt[1] ? -(g_acc[3] / (g_acc[2] > 0.0 ? g_acc[2] : 1.0)) : -0.0001;
    double l3 = g_cnt[2] ? -(g_acc[5] / (g_acc[4] > 0.0 ? g_acc[4] : 1.0)) : -0.0001;
    double lp = g_cnt[3] ?  (g_acc[7] / (g_acc[6] != 0.0 ? g_acc[6] : 1.0)) :  0.0001;
    out[(size_t)Bn * Bn] = (float)(1.0 + (l1 + l2 + l3 + lp) * 0.25);
}

extern "C" void kernel_launch(void* const* d_in, const int* in_sizes, int n_in,
                              void* d_out, int out_size) {
    const float* x     = (const float*)d_in[0];
    const int*   y     = (const int*)d_in[1];
    const float* mean  = (const float*)d_in[2];
    const float* stdv  = (const float*)d_in[3];
    const float* noise = (const float*)d_in[4];
    float* out = (float*)d_out;

    prep_kernel<<<Bn / (TPB / 32), TPB>>>(x);
    dim3 grid(Bn / TILE, Bn / TILE);
    dist_loss_kernel<<<grid, TPB>>>(x, y, mean, stdv, noise, out);
    finalize_kernel<<<1, 1>>>(out);
}

// round 6
// speedup vs baseline: 3.5380x; 1.1744x over previous
#include <cuda_runtime.h>
#include <cuda_bf16.h>
#include <math.h>
#include <stdint.h>

#define Bn 4096
#define DF 128
#define NC 512
#define TILE 128
#define TPB 256
#define TS 68           // bf16 tile row stride in 32-bit words (= 136 bf16)
#define SS 132          // f32 staging row stride in words

// smem layout (dynamic)
#define OFF_SQJ 0        // f32[128]
#define OFF_YJ  512      // int[128]
#define OFF_SQI 1024     // f32[128]
#define OFF_YI  1536     // int[128]
#define OFF_AH  2048     // 34816 B each tile (128 rows x 136 bf16)
#define OFF_AL  36864
#define OFF_BH  71680
#define OFF_BL  106496
#define SMEM_TOTAL 141312
#define OFF_SD  OFF_AH   // staging direct: 128 x 132 f32 = 67584 (fits AH+AL)
#define OFF_ST  OFF_BH   // staging transposed: 67584 (fits BH+BL)

// ---------------- device scratch ----------------
__device__ double g_acc[8];
__device__ unsigned long long g_cnt[4];
__device__ float g_sq[Bn];
__device__ __nv_bfloat16 g_xh[Bn * DF];
__device__ __nv_bfloat16 g_xl[Bn * DF];

// bf16 m16n8k16 HMMA (standard PTX, works on plain sm_103 target)
__device__ __forceinline__ void mma16816(float* c, const uint32_t* a, const uint32_t* b) {
    asm volatile(
        "mma.sync.aligned.m16n8k16.row.col.f32.bf16.bf16.f32 "
        "{%0,%1,%2,%3}, {%4,%5,%6,%7}, {%8,%9}, {%0,%1,%2,%3};"
        : "+f"(c[0]), "+f"(c[1]), "+f"(c[2]), "+f"(c[3])
        : "r"(a[0]), "r"(a[1]), "r"(a[2]), "r"(a[3]), "r"(b[0]), "r"(b[1]));
}

// exp(logit), logit in [0, ~250]: fp32 exp2 mantissa * bit-built double scale
__device__ __forceinline__ double fast_exp_pos(float logit) {
    float arg = logit * 1.4426950408889634f;
    float fi = floorf(arg);
    float fr = arg - fi;
    long long e = (long long)(1023 + (int)fi) << 52;
    return __longlong_as_double(e) * (double)exp2f(fr);
}

__device__ __forceinline__ double wredd(double v) {
#pragma unroll
    for (int o = 16; o; o >>= 1) v += __shfl_xor_sync(0xffffffffu, v, o);
    return v;
}
__device__ __forceinline__ unsigned wredu(unsigned v) {
#pragma unroll
    for (int o = 16; o; o >>= 1) v += __shfl_xor_sync(0xffffffffu, v, o);
    return v;
}

// negative-pair loss contribution
__device__ __forceinline__ void neg_term(float d, float cm, float cs, float nz,
                                         double* p, unsigned* cc) {
    const float obs  = fmaf(cs, nz, cm);
    const float tn1  = obs - 2.5f * cs;
    const float tmid = obs - 1.5f * cs;
    if (d < tn1) {
        double w = fast_exp_pos(10.f * (tn1 - d));
        p[0] += w; p[1] += w * (double)d; cc[0]++;
    } else if (d > tn1 && d < tmid) {
        double w = fast_exp_pos(5.f * (tmid - d));
        p[2] += w; p[3] += w * (double)d; cc[1]++;
    } else {
        const float thi = obs + 1.5f * cs;
        if (d > tmid && d < thi) {
            double w = fast_exp_pos(5.f * (thi - d));
            p[4] += w; p[5] += w * (double)d; cc[2]++;
        }
    }
}

// ---------------------------------------------------------------------------
// prep: zero accumulators, row squared norms, bf16 hi/lo split
// ---------------------------------------------------------------------------
__global__ void __launch_bounds__(TPB) prep_kernel(const float* __restrict__ x) {
    if (blockIdx.x == 0 && threadIdx.x < 12) {
        if (threadIdx.x < 8) g_acc[threadIdx.x] = 0.0;
        else                 g_cnt[threadIdx.x - 8] = 0ull;
    }
    int row  = blockIdx.x * (TPB / 32) + (threadIdx.x >> 5);
    int lane = threadIdx.x & 31;
    float4 v = ((const float4*)(x + (size_t)row * DF))[lane];
    float s = v.x * v.x + v.y * v.y + v.z * v.z + v.w * v.w;
#pragma unroll
    for (int o = 16; o; o >>= 1) s += __shfl_xor_sync(0xffffffffu, s, o);
    if (lane == 0) g_sq[row] = s;

    float vv[4] = {v.x, v.y, v.z, v.w};
    __nv_bfloat16 h[4], l[4];
#pragma unroll
    for (int q = 0; q < 4; q++) {
        h[q] = __float2bfloat16(vv[q]);
        l[q] = __float2bfloat16(vv[q] - __bfloat162float(h[q]));
    }
    uint2 ph, pl;
    ph.x = ((uint32_t)__bfloat16_as_ushort(h[1]) << 16) | __bfloat16_as_ushort(h[0]);
    ph.y = ((uint32_t)__bfloat16_as_ushort(h[3]) << 16) | __bfloat16_as_ushort(h[2]);
    pl.x = ((uint32_t)__bfloat16_as_ushort(l[1]) << 16) | __bfloat16_as_ushort(l[0]);
    pl.y = ((uint32_t)__bfloat16_as_ushort(l[3]) << 16) | __bfloat16_as_ushort(l[2]);
    ((uint2*)(g_xh + (size_t)row * DF))[lane] = ph;
    ((uint2*)(g_xl + (size_t)row * DF))[lane] = pl;
}

// ---------------------------------------------------------------------------
// fused tile kernel: HMMA GEMM (bf16 hi/lo) + dist stores + loss
// ---------------------------------------------------------------------------
__global__ void __launch_bounds__(TPB, 1)
dist_loss_kernel(const int* __restrict__ y,
                 const float* __restrict__ mean, const float* __restrict__ stdv,
                 const float* __restrict__ noise, float* __restrict__ out)
{
    const int bi = blockIdx.y, bj = blockIdx.x;
    if (bj < bi) return;
    const int i0 = bi * TILE, j0 = bj * TILE;
    const bool diag = (bi == bj);

    extern __shared__ char smem[];
    __shared__ double sred[8][8];
    __shared__ unsigned scnt[8][4];

    const int tid  = threadIdx.x;
    const int wid  = tid >> 5;
    const int lane = tid & 31;
    const int g    = lane >> 2;       // group id 0..7
    const int tg   = lane & 3;        // thread in group
    const int wm   = wid >> 2;        // warp m-stripe (0/1): rows wm*64..+64
    const int wn   = wid & 3;         // warp n-stripe: cols wn*32..+32

    // panels
    if (tid < 128) {
        ((float*)(smem + OFF_SQJ))[tid] = g_sq[j0 + tid];
        ((int*)(smem + OFF_YJ))[tid]    = y[j0 + tid];
        ((float*)(smem + OFF_SQI))[tid] = g_sq[i0 + tid];
        ((int*)(smem + OFF_YI))[tid]    = y[i0 + tid];
    }

    // load 4 bf16 tiles (row stride 136 bf16 = 17 uint4)
    {
        const __nv_bfloat16* srcs[4] = {g_xh + (size_t)i0 * DF, g_xl + (size_t)i0 * DF,
                                        g_xh + (size_t)j0 * DF, g_xl + (size_t)j0 * DF};
        const uint32_t dsts[4] = {OFF_AH, OFF_AL, OFF_BH, OFF_BL};
#pragma unroll
        for (int t4 = 0; t4 < 4; t4++) {
            const uint4* src = (const uint4*)srcs[t4];
            uint4* dst = (uint4*)(smem + dsts[t4]);
#pragma unroll
            for (int t = 0; t < 8; t++) {
                int idx = tid + t * TPB;              // 0..2047 16B chunks
                int row = idx >> 4, ch = idx & 15;
                dst[row * 17 + ch] = src[row * 16 + ch];
            }
        }
    }
    __syncthreads();

    const uint32_t* Ah = (const uint32_t*)(smem + OFF_AH);
    const uint32_t* Al = (const uint32_t*)(smem + OFF_AL);
    const uint32_t* Bh = (const uint32_t*)(smem + OFF_BH);
    const uint32_t* Bl = (const uint32_t*)(smem + OFF_BL);

    float acc[16][4];
#pragma unroll
    for (int q = 0; q < 16; q++)
#pragma unroll
        for (int e = 0; e < 4; e++) acc[q][e] = 0.f;

    // D = Ah*Bh^T + Ah*Bl^T + Al*Bh^T
#pragma unroll
    for (int pass = 0; pass < 3; pass++) {
        const uint32_t* A = (pass < 2) ? Ah : Al;
        const uint32_t* B = (pass == 1) ? Bl : Bh;
#pragma unroll
        for (int ks = 0; ks < 8; ks++) {
            uint32_t af[4][4], bf[4][2];
#pragma unroll
            for (int mt = 0; mt < 4; mt++) {
                const int r = wm * 64 + mt * 16 + g;
                const uint32_t* ap = A + r * TS + tg + 8 * ks;
                af[mt][0] = ap[0];
                af[mt][1] = ap[8 * TS];
                af[mt][2] = ap[4];
                af[mt][3] = ap[8 * TS + 4];
            }
#pragma unroll
            for (int nt = 0; nt < 4; nt++) {
                const int rb = wn * 32 + nt * 8 + g;
                const uint32_t* bp = B + rb * TS + tg + 8 * ks;
                bf[nt][0] = bp[0];
                bf[nt][1] = bp[4];
            }
#pragma unroll
            for (int mt = 0; mt < 4; mt++)
#pragma unroll
                for (int nt = 0; nt < 4; nt++)
                    mma16816(acc[mt * 4 + nt], af[mt], bf[nt]);
        }
    }
    __syncthreads();   // all warps done reading tiles; staging reuses them

    const float* s_sqj = (const float*)(smem + OFF_SQJ);
    const int*   s_yj  = (const int*)(smem + OFF_YJ);
    const float* s_sqi = (const float*)(smem + OFF_SQI);
    const int*   s_yi  = (const int*)(smem + OFF_YI);
    float* Sd = (float*)(smem + OFF_SD);
    float* St = (float*)(smem + OFF_ST);

    double p[8] = {0, 0, 0, 0, 0, 0, 0, 0};
    unsigned cc4[4] = {0, 0, 0, 0};

#pragma unroll
    for (int mt = 0; mt < 4; mt++) {
        const int r0 = wm * 64 + mt * 16 + g, r1 = r0 + 8;
        const int ia = i0 + r0, ib = i0 + r1;
        const float sqa = s_sqi[r0], sqb = s_sqi[r1];
        const float* mra = mean + (size_t)s_yi[r0] * NC;
        const float* sra = stdv + (size_t)s_yi[r0] * NC;
        const float* mrb = mean + (size_t)s_yi[r1] * NC;
        const float* srb = stdv + (size_t)s_yi[r1] * NC;
        const float* nra = noise + (size_t)ia * Bn;
        const float* nrb = noise + (size_t)ib * Bn;
#pragma unroll
        for (int nt = 0; nt < 4; nt++) {
            const int c = wn * 32 + nt * 8 + 2 * tg;
            const int j = j0 + c;
            const float* a = acc[mt * 4 + nt];
            const float d00 = sqa + s_sqj[c]     - 2.f * a[0];
            const float d01 = sqa + s_sqj[c + 1] - 2.f * a[1];
            const float d10 = sqb + s_sqj[c]     - 2.f * a[2];
            const float d11 = sqb + s_sqj[c + 1] - 2.f * a[3];
            *(float2*)&Sd[r0 * SS + c] = make_float2(d00, d01);
            *(float2*)&Sd[r1 * SS + c] = make_float2(d10, d11);
            if (!diag) {
                St[c * SS + r0] = d00; St[(c + 1) * SS + r0] = d01;
                St[c * SS + r1] = d10; St[(c + 1) * SS + r1] = d11;
            }
            const int yj0 = s_yj[c], yj1 = s_yj[c + 1];
            const float2 na = *(const float2*)(nra + j);
            const float2 nb = *(const float2*)(nrb + j);
            const float cma0 = __ldg(&mra[yj0]), csa0 = __ldg(&sra[yj0]);
            const float cma1 = __ldg(&mra[yj1]), csa1 = __ldg(&sra[yj1]);
            const float cmb0 = __ldg(&mrb[yj0]), csb0 = __ldg(&srb[yj0]);
            const float cmb1 = __ldg(&mrb[yj1]), csb1 = __ldg(&srb[yj1]);
            if (!diag) {          // all pairs negative, all j>i
                neg_term(d00, cma0, csa0, na.x, p, cc4);
                neg_term(d01, cma1, csa1, na.y, p, cc4);
                neg_term(d10, cmb0, csb0, nb.x, p, cc4);
                neg_term(d11, cmb1, csb1, nb.y, p, cc4);
            } else {
                const int gia = ia >> 3, gib = ib >> 3;
#define DIAG_ELEM(jj, dd, cm, cs, nz, ii, gg)                                   \
                if ((jj) > (ii)) {                                              \
                    if (((jj) >> 3) != (gg)) neg_term(dd, cm, cs, nz, p, cc4);  \
                    else {                                                      \
                        const float obs = fmaf(cs, nz, cm);                     \
                        const float tp = obs + 2.0f * cs;                       \
                        if ((dd) > tp) {                                        \
                            p[6] += (double)(dd);                               \
                            p[7] += (double)(dd) * (double)(dd); cc4[3]++;      \
                        }                                                       \
                    }                                                           \
                }
                DIAG_ELEM(j,     d00, cma0, csa0, na.x, ia, gia)
                DIAG_ELEM(j + 1, d01, cma1, csa1, na.y, ia, gia)
                DIAG_ELEM(j,     d10, cmb0, csb0, nb.x, ib, gib)
                DIAG_ELEM(j + 1, d11, cmb1, csb1, nb.y, ib, gib)
#undef DIAG_ELEM
            }
        }
    }
    __syncthreads();

    // coalesced global stores from staging
#pragma unroll
    for (int t = 0; t < 16; t++) {
        const int idx = tid + t * TPB;            // 0..4095 float4 units
        const int r = idx >> 5, c4 = (idx & 31) * 4;
        *(float4*)&out[(size_t)(i0 + r) * Bn + j0 + c4] = *(float4*)&Sd[r * SS + c4];
    }
    if (!diag) {
#pragma unroll
        for (int t = 0; t < 16; t++) {
            const int idx = tid + t * TPB;
            const int jr = idx >> 5, c4 = (idx & 31) * 4;
            *(float4*)&out[(size_t)(j0 + jr) * Bn + i0 + c4] = *(float4*)&St[jr * SS + c4];
        }
    }

    // block reduce + global atomics
#pragma unroll
    for (int q = 0; q < 8; q++) p[q] = wredd(p[q]);
#pragma unroll
    for (int q = 0; q < 4; q++) cc4[q] = wredu(cc4[q]);
    if (lane == 0) {
#pragma unroll
        for (int q = 0; q < 8; q++) sred[wid][q] = p[q];
#pragma unroll
        for (int q = 0; q < 4; q++) scnt[wid][q] = cc4[q];
    }
    __syncthreads();
    if (tid < 8) {
        double s = 0;
#pragma unroll
        for (int w = 0; w < 8; w++) s += sred[w][tid];
        if (s != 0.0) atomicAdd(&g_acc[tid], s);
    } else if (tid < 12) {
        unsigned long long s = 0;
#pragma unroll
        for (int w = 0; w < 8; w++) s += scnt[w][tid - 8];
        if (s) atomicAdd(&g_cnt[tid - 8], s);
    }
}

// ---------------------------------------------------------------------------
__global__ void finalize_kernel(float* __restrict__ out) {
    double l1 = g_cnt[0] ? -(g_acc[1] / (g_acc[0] > 0.0 ? g_acc[0] : 1.0)) : -0.0001;
    double l2 = g_cnt[1] ? -(g_acc[3] / (g_acc[2] > 0.0 ? g_acc[2] : 1.0)) : -0.0001;
    double l3 = g_cnt[2] ? -(g_acc[5] / (g_acc[4] > 0.0 ? g_acc[4] : 1.0)) : -0.0001;
    double lp = g_cnt[3] ?  (g_acc[7] / (g_acc[6] != 0.0 ? g_acc[6] : 1.0)) :  0.0001;
    out[(size_t)Bn * Bn] = (float)(1.0 + (l1 + l2 + l3 + lp) * 0.25);
}

extern "C" void kernel_launch(void* const* d_in, const int* in_sizes, int n_in,
                              void* d_out, int out_size) {
    const float* x     = (const float*)d_in[0];
    const int*   y     = (const int*)d_in[1];
    const float* mean  = (const float*)d_in[2];
    const float* stdv  = (const float*)d_in[3];
    const float* noise = (const float*)d_in[4];
    float* out = (float*)d_out;

    cudaFuncSetAttribute(dist_loss_kernel, cudaFuncAttributeMaxDynamicSharedMemorySize,
                         SMEM_TOTAL);

    prep_kernel<<<Bn / (TPB / 32), TPB>>>(x);
    dim3 grid(Bn / TILE, Bn / TILE);
    dist_loss_kernel<<<grid, TPB, SMEM_TOTAL>>>(y, mean, stdv, noise, out);
    finalize_kernel<<<1, 1>>>(out);
}

// round 7
// speedup vs baseline: 3.5417x; 1.0010x over previous
#include <cuda_runtime.h>
#include <cuda_bf16.h>
#include <math.h>
#include <stdint.h>

#define Bn 4096
#define DF 128
#define NC 512
#define TILE 128
#define TPB 256
#define TS 68           // bf16 tile row stride in 32-bit words (= 136 bf16)
#define SS 132          // f32 staging row stride in words

// smem layout (dynamic)
#define OFF_SQJ 0        // f32[128]
#define OFF_YJ  512      // int[128]
#define OFF_SQI 1024     // f32[128]
#define OFF_YI  1536     // int[128]
#define OFF_AH  2048     // 34816 B each tile (128 rows x 136 bf16)
#define OFF_AL  36864
#define OFF_BH  71680
#define OFF_BL  106496
#define SMEM_TOTAL 141312
#define OFF_SD  OFF_AH   // staging direct: 128 x 132 f32 = 67584 (fits AH+AL)
#define OFF_ST  OFF_BH   // staging transposed: 67584 (fits BH+BL)

// ---------------- device scratch ----------------
__device__ double g_acc[8];
__device__ unsigned long long g_cnt[4];
__device__ float g_sq[Bn];
__device__ __nv_bfloat16 g_xh[Bn * DF];
__device__ __nv_bfloat16 g_xl[Bn * DF];

// bf16 m16n8k16 HMMA (standard PTX, works on plain sm_103 target)
__device__ __forceinline__ void mma16816(float* c, const uint32_t* a, const uint32_t* b) {
    asm volatile(
        "mma.sync.aligned.m16n8k16.row.col.f32.bf16.bf16.f32 "
        "{%0,%1,%2,%3}, {%4,%5,%6,%7}, {%8,%9}, {%0,%1,%2,%3};"
        : "+f"(c[0]), "+f"(c[1]), "+f"(c[2]), "+f"(c[3])
        : "r"(a[0]), "r"(a[1]), "r"(a[2]), "r"(a[3]), "r"(b[0]), "r"(b[1]));
}

// exp(logit), logit in [0, ~250]: fp32 exp2 mantissa * bit-built double scale
__device__ __forceinline__ double fast_exp_pos(float logit) {
    float arg = logit * 1.4426950408889634f;
    float fi = floorf(arg);
    float fr = arg - fi;
    long long e = (long long)(1023 + (int)fi) << 52;
    return __longlong_as_double(e) * (double)exp2f(fr);
}

__device__ __forceinline__ double wredd(double v) {
#pragma unroll
    for (int o = 16; o; o >>= 1) v += __shfl_xor_sync(0xffffffffu, v, o);
    return v;
}
__device__ __forceinline__ unsigned wredu(unsigned v) {
#pragma unroll
    for (int o = 16; o; o >>= 1) v += __shfl_xor_sync(0xffffffffu, v, o);
    return v;
}

// negative-pair loss contribution
__device__ __forceinline__ void neg_term(float d, float cm, float cs, float nz,
                                         double* p, unsigned* cc) {
    const float obs  = fmaf(cs, nz, cm);
    const float tn1  = obs - 2.5f * cs;
    const float tmid = obs - 1.5f * cs;
    if (d < tn1) {
        double w = fast_exp_pos(10.f * (tn1 - d));
        p[0] += w; p[1] += w * (double)d; cc[0]++;
    } else if (d > tn1 && d < tmid) {
        double w = fast_exp_pos(5.f * (tmid - d));
        p[2] += w; p[3] += w * (double)d; cc[1]++;
    } else {
        const float thi = obs + 1.5f * cs;
        if (d > tmid && d < thi) {
            double w = fast_exp_pos(5.f * (thi - d));
            p[4] += w; p[5] += w * (double)d; cc[2]++;
        }
    }
}

// ---------------------------------------------------------------------------
// prep: zero accumulators, row squared norms, bf16 hi/lo split
// ---------------------------------------------------------------------------
__global__ void __launch_bounds__(TPB) prep_kernel(const float* __restrict__ x) {
    if (blockIdx.x == 0 && threadIdx.x < 12) {
        if (threadIdx.x < 8) g_acc[threadIdx.x] = 0.0;
        else                 g_cnt[threadIdx.x - 8] = 0ull;
    }
    int row  = blockIdx.x * (TPB / 32) + (threadIdx.x >> 5);
    int lane = threadIdx.x & 31;
    float4 v = ((const float4*)(x + (size_t)row * DF))[lane];
    float s = v.x * v.x + v.y * v.y + v.z * v.z + v.w * v.w;
#pragma unroll
    for (int o = 16; o; o >>= 1) s += __shfl_xor_sync(0xffffffffu, s, o);
    if (lane == 0) g_sq[row] = s;

    float vv[4] = {v.x, v.y, v.z, v.w};
    __nv_bfloat16 h[4], l[4];
#pragma unroll
    for (int q = 0; q < 4; q++) {
        h[q] = __float2bfloat16(vv[q]);
        l[q] = __float2bfloat16(vv[q] - __bfloat162float(h[q]));
    }
    uint2 ph, pl;
    ph.x = ((uint32_t)__bfloat16_as_ushort(h[1]) << 16) | __bfloat16_as_ushort(h[0]);
    ph.y = ((uint32_t)__bfloat16_as_ushort(h[3]) << 16) | __bfloat16_as_ushort(h[2]);
    pl.x = ((uint32_t)__bfloat16_as_ushort(l[1]) << 16) | __bfloat16_as_ushort(l[0]);
    pl.y = ((uint32_t)__bfloat16_as_ushort(l[3]) << 16) | __bfloat16_as_ushort(l[2]);
    ((uint2*)(g_xh + (size_t)row * DF))[lane] = ph;
    ((uint2*)(g_xl + (size_t)row * DF))[lane] = pl;
}

// ---------------------------------------------------------------------------
// fused tile kernel: HMMA GEMM (bf16 hi/lo) + dist stores + loss
// ---------------------------------------------------------------------------
__global__ void __launch_bounds__(TPB, 1)
dist_loss_kernel(const int* __restrict__ y,
                 const float* __restrict__ mean, const float* __restrict__ stdv,
                 const float* __restrict__ noise, float* __restrict__ out)
{
    const int bi = blockIdx.y, bj = blockIdx.x;
    if (bj < bi) return;
    const int i0 = bi * TILE, j0 = bj * TILE;
    const bool diag = (bi == bj);

    extern __shared__ char smem[];
    __shared__ double sred[8][8];
    __shared__ unsigned scnt[8][4];

    const int tid  = threadIdx.x;
    const int wid  = tid >> 5;
    const int lane = tid & 31;
    const int g    = lane >> 2;       // group id 0..7
    const int tg   = lane & 3;        // thread in group
    const int wm   = wid >> 2;        // warp m-stripe (0/1): rows wm*64..+64
    const int wn   = wid & 3;         // warp n-stripe: cols wn*32..+32

    // panels
    if (tid < 128) {
        ((float*)(smem + OFF_SQJ))[tid] = g_sq[j0 + tid];
        ((int*)(smem + OFF_YJ))[tid]    = y[j0 + tid];
        ((float*)(smem + OFF_SQI))[tid] = g_sq[i0 + tid];
        ((int*)(smem + OFF_YI))[tid]    = y[i0 + tid];
    }

    // load 4 bf16 tiles (row stride 136 bf16 = 17 uint4)
    {
        const __nv_bfloat16* srcs[4] = {g_xh + (size_t)i0 * DF, g_xl + (size_t)i0 * DF,
                                        g_xh + (size_t)j0 * DF, g_xl + (size_t)j0 * DF};
        const uint32_t dsts[4] = {OFF_AH, OFF_AL, OFF_BH, OFF_BL};
#pragma unroll
        for (int t4 = 0; t4 < 4; t4++) {
            const uint4* src = (const uint4*)srcs[t4];
            uint4* dst = (uint4*)(smem + dsts[t4]);
#pragma unroll
            for (int t = 0; t < 8; t++) {
                int idx = tid + t * TPB;              // 0..2047 16B chunks
                int row = idx >> 4, ch = idx & 15;
                dst[row * 17 + ch] = src[row * 16 + ch];
            }
        }
    }
    __syncthreads();

    const uint32_t* Ah = (const uint32_t*)(smem + OFF_AH);
    const uint32_t* Al = (const uint32_t*)(smem + OFF_AL);
    const uint32_t* Bh = (const uint32_t*)(smem + OFF_BH);
    const uint32_t* Bl = (const uint32_t*)(smem + OFF_BL);

    float acc[16][4];
#pragma unroll
    for (int q = 0; q < 16; q++)
#pragma unroll
        for (int e = 0; e < 4; e++) acc[q][e] = 0.f;

    // D = Ah*Bh^T + Ah*Bl^T + Al*Bh^T
#pragma unroll
    for (int pass = 0; pass < 3; pass++) {
        const uint32_t* A = (pass < 2) ? Ah : Al;
        const uint32_t* B = (pass == 1) ? Bl : Bh;
#pragma unroll
        for (int ks = 0; ks < 8; ks++) {
            uint32_t af[4][4], bf[4][2];
#pragma unroll
            for (int mt = 0; mt < 4; mt++) {
                const int r = wm * 64 + mt * 16 + g;
                const uint32_t* ap = A + r * TS + tg + 8 * ks;
                af[mt][0] = ap[0];
                af[mt][1] = ap[8 * TS];
                af[mt][2] = ap[4];
                af[mt][3] = ap[8 * TS + 4];
            }
#pragma unroll
            for (int nt = 0; nt < 4; nt++) {
                const int rb = wn * 32 + nt * 8 + g;
                const uint32_t* bp = B + rb * TS + tg + 8 * ks;
                bf[nt][0] = bp[0];
                bf[nt][1] = bp[4];
            }
#pragma unroll
            for (int mt = 0; mt < 4; mt++)
#pragma unroll
                for (int nt = 0; nt < 4; nt++)
                    mma16816(acc[mt * 4 + nt], af[mt], bf[nt]);
        }
    }
    __syncthreads();   // all warps done reading tiles; staging reuses them

    const float* s_sqj = (const float*)(smem + OFF_SQJ);
    const int*   s_yj  = (const int*)(smem + OFF_YJ);
    const float* s_sqi = (const float*)(smem + OFF_SQI);
    const int*   s_yi  = (const int*)(smem + OFF_YI);
    float* Sd = (float*)(smem + OFF_SD);
    float* St = (float*)(smem + OFF_ST);

    double p[8] = {0, 0, 0, 0, 0, 0, 0, 0};
    unsigned cc4[4] = {0, 0, 0, 0};

#pragma unroll
    for (int mt = 0; mt < 4; mt++) {
        const int r0 = wm * 64 + mt * 16 + g, r1 = r0 + 8;
        const int ia = i0 + r0, ib = i0 + r1;
        const float sqa = s_sqi[r0], sqb = s_sqi[r1];
        const float* mra = mean + (size_t)s_yi[r0] * NC;
        const float* sra = stdv + (size_t)s_yi[r0] * NC;
        const float* mrb = mean + (size_t)s_yi[r1] * NC;
        const float* srb = stdv + (size_t)s_yi[r1] * NC;
        const float* nra = noise + (size_t)ia * Bn;
        const float* nrb = noise + (size_t)ib * Bn;
#pragma unroll
        for (int nt = 0; nt < 4; nt++) {
            const int c = wn * 32 + nt * 8 + 2 * tg;
            const int j = j0 + c;
            const float* a = acc[mt * 4 + nt];
            const float d00 = sqa + s_sqj[c]     - 2.f * a[0];
            const float d01 = sqa + s_sqj[c + 1] - 2.f * a[1];
            const float d10 = sqb + s_sqj[c]     - 2.f * a[2];
            const float d11 = sqb + s_sqj[c + 1] - 2.f * a[3];
            *(float2*)&Sd[r0 * SS + c] = make_float2(d00, d01);
            *(float2*)&Sd[r1 * SS + c] = make_float2(d10, d11);
            if (!diag) {
                St[c * SS + r0] = d00; St[(c + 1) * SS + r0] = d01;
                St[c * SS + r1] = d10; St[(c + 1) * SS + r1] = d11;
            }
            const int yj0 = s_yj[c], yj1 = s_yj[c + 1];
            const float2 na = *(const float2*)(nra + j);
            const float2 nb = *(const float2*)(nrb + j);
            const float cma0 = __ldg(&mra[yj0]), csa0 = __ldg(&sra[yj0]);
            const float cma1 = __ldg(&mra[yj1]), csa1 = __ldg(&sra[yj1]);
            const float cmb0 = __ldg(&mrb[yj0]), csb0 = __ldg(&srb[yj0]);
            const float cmb1 = __ldg(&mrb[yj1]), csb1 = __ldg(&srb[yj1]);
            if (!diag) {          // all pairs negative, all j>i
                neg_term(d00, cma0, csa0, na.x, p, cc4);
                neg_term(d01, cma1, csa1, na.y, p, cc4);
                neg_term(d10, cmb0, csb0, nb.x, p, cc4);
                neg_term(d11, cmb1, csb1, nb.y, p, cc4);
            } else {
                const int gia = ia >> 3, gib = ib >> 3;
#define DIAG_ELEM(jj, dd, cm, cs, nz, ii, gg)                                   \
                if ((jj) > (ii)) {                                              \
                    if (((jj) >> 3) != (gg)) neg_term(dd, cm, cs, nz, p, cc4);  \
                    else {                                                      \
                        const float obs = fmaf(cs, nz, cm);                     \
                        const float tp = obs + 2.0f * cs;                       \
                        if ((dd) > tp) {                                        \
                            p[6] += (double)(dd);                               \
                            p[7] += (double)(dd) * (double)(dd); cc4[3]++;      \
                        }                                                       \
                    }                                                           \
                }
                DIAG_ELEM(j,     d00, cma0, csa0, na.x, ia, gia)
                DIAG_ELEM(j + 1, d01, cma1, csa1, na.y, ia, gia)
                DIAG_ELEM(j,     d10, cmb0, csb0, nb.x, ib, gib)
                DIAG_ELEM(j + 1, d11, cmb1, csb1, nb.y, ib, gib)
#undef DIAG_ELEM
            }
        }
    }
    __syncthreads();

    // coalesced global stores from staging
#pragma unroll
    for (int t = 0; t < 16; t++) {
        const int idx = tid + t * TPB;            // 0..4095 float4 units
        const int r = idx >> 5, c4 = (idx & 31) * 4;
        *(float4*)&out[(size_t)(i0 + r) * Bn + j0 + c4] = *(float4*)&Sd[r * SS + c4];
    }
    if (!diag) {
#pragma unroll
        for (int t = 0; t < 16; t++) {
            const int idx = tid + t * TPB;
            const int jr = idx >> 5, c4 = (idx & 31) * 4;
            *(float4*)&out[(size_t)(j0 + jr) * Bn + i0 + c4] = *(float4*)&St[jr * SS + c4];
        }
    }

    // block reduce + global atomics
#pragma unroll
    for (int q = 0; q < 8; q++) p[q] = wredd(p[q]);
#pragma unroll
    for (int q = 0; q < 4; q++) cc4[q] = wredu(cc4[q]);
    if (lane == 0) {
#pragma unroll
        for (int q = 0; q < 8; q++) sred[wid][q] = p[q];
#pragma unroll
        for (int q = 0; q < 4; q++) scnt[wid][q] = cc4[q];
    }
    __syncthreads();
    if (tid < 8) {
        double s = 0;
#pragma unroll
        for (int w = 0; w < 8; w++) s += sred[w][tid];
        if (s != 0.0) atomicAdd(&g_acc[tid], s);
    } else if (tid < 12) {
        unsigned long long s = 0;
#pragma unroll
        for (int w = 0; w < 8; w++) s += scnt[w][tid - 8];
        if (s) atomicAdd(&g_cnt[tid - 8], s);
    }
}

// ---------------------------------------------------------------------------
__global__ void finalize_kernel(float* __restrict__ out) {
    double l1 = g_cnt[0] ? -(g_acc[1] / (g_acc[0] > 0.0 ? g_acc[0] : 1.0)) : -0.0001;
    double l2 = g_cnt[1] ? -(g_acc[3] / (g_acc[2] > 0.0 ? g_acc[2] : 1.0)) : -0.0001;
    double l3 = g_cnt[2] ? -(g_acc[5] / (g_acc[4] > 0.0 ? g_acc[4] : 1.0)) : -0.0001;
    double lp = g_cnt[3] ?  (g_acc[7] / (g_acc[6] != 0.0 ? g_acc[6] : 1.0)) :  0.0001;
    out[(size_t)Bn * Bn] = (float)(1.0 + (l1 + l2 + l3 + lp) * 0.25);
}

extern "C" void kernel_launch(void* const* d_in, const int* in_sizes, int n_in,
                              void* d_out, int out_size) {
    const float* x     = (const float*)d_in[0];
    const int*   y     = (const int*)d_in[1];
    const float* mean  = (const float*)d_in[2];
    const float* stdv  = (const float*)d_in[3];
    const float* noise = (const float*)d_in[4];
    float* out = (float*)d_out;

    cudaFuncSetAttribute(dist_loss_kernel, cudaFuncAttributeMaxDynamicSharedMemorySize,
                         SMEM_TOTAL);

    prep_kernel<<<Bn / (TPB / 32), TPB>>>(x);
    dim3 grid(Bn / TILE, Bn / TILE);
    dist_loss_kernel<<<grid, TPB, SMEM_TOTAL>>>(y, mean, stdv, noise, out);
    finalize_kernel<<<1, 1>>>(out);
}

// round 8
// speedup vs baseline: 3.5423x; 1.0002x over previous
#include <cuda_runtime.h>
#include <cuda_bf16.h>
#include <math.h>
#include <stdint.h>

#define Bn 4096
#define DF 128
#define NC 512
#define TILE 128
#define TPB 256
#define TS 68           // bf16 tile row stride in 32-bit words (= 136 bf16)
#define SS 132          // f32 staging row stride in words

// smem layout (dynamic)
#define OFF_SQJ 0        // f32[128]
#define OFF_YJ  512      // int[128]
#define OFF_SQI 1024     // f32[128]
#define OFF_YI  1536     // int[128]
#define OFF_AH  2048     // 34816 B each tile (128 rows x 136 bf16)
#define OFF_AL  36864
#define OFF_BH  71680
#define OFF_BL  106496
#define SMEM_TOTAL 141312
#define OFF_SD  OFF_AH   // staging direct: 128 x 132 f32 = 67584 (fits AH+AL)
#define OFF_ST  OFF_BH   // staging transposed: 67584 (fits BH+BL)

// ---------------- device scratch ----------------
__device__ double g_acc[8];
__device__ unsigned long long g_cnt[4];
__device__ float g_sq[Bn];
__device__ __nv_bfloat16 g_xh[Bn * DF];
__device__ __nv_bfloat16 g_xl[Bn * DF];

// bf16 m16n8k16 HMMA (standard PTX, works on plain sm_103 target)
__device__ __forceinline__ void mma16816(float* c, const uint32_t* a, const uint32_t* b) {
    asm volatile(
        "mma.sync.aligned.m16n8k16.row.col.f32.bf16.bf16.f32 "
        "{%0,%1,%2,%3}, {%4,%5,%6,%7}, {%8,%9}, {%0,%1,%2,%3};"
        : "+f"(c[0]), "+f"(c[1]), "+f"(c[2]), "+f"(c[3])
        : "r"(a[0]), "r"(a[1]), "r"(a[2]), "r"(a[3]), "r"(b[0]), "r"(b[1]));
}

// exp(logit), logit in [0, ~250]: fp32 exp2 mantissa * bit-built double scale
__device__ __forceinline__ double fast_exp_pos(float logit) {
    float arg = logit * 1.4426950408889634f;
    float fi = floorf(arg);
    float fr = arg - fi;
    long long e = (long long)(1023 + (int)fi) << 52;
    return __longlong_as_double(e) * (double)exp2f(fr);
}

__device__ __forceinline__ double wredd(double v) {
#pragma unroll
    for (int o = 16; o; o >>= 1) v += __shfl_xor_sync(0xffffffffu, v, o);
    return v;
}
__device__ __forceinline__ unsigned wredu(unsigned v) {
#pragma unroll
    for (int o = 16; o; o >>= 1) v += __shfl_xor_sync(0xffffffffu, v, o);
    return v;
}

// negative-pair loss contribution
__device__ __forceinline__ void neg_term(float d, float cm, float cs, float nz,
                                         double* p, unsigned* cc) {
    const float obs  = fmaf(cs, nz, cm);
    const float tn1  = obs - 2.5f * cs;
    const float tmid = obs - 1.5f * cs;
    if (d < tn1) {
        double w = fast_exp_pos(10.f * (tn1 - d));
        p[0] += w; p[1] += w * (double)d; cc[0]++;
    } else if (d > tn1 && d < tmid) {
        double w = fast_exp_pos(5.f * (tmid - d));
        p[2] += w; p[3] += w * (double)d; cc[1]++;
    } else {
        const float thi = obs + 1.5f * cs;
        if (d > tmid && d < thi) {
            double w = fast_exp_pos(5.f * (thi - d));
            p[4] += w; p[5] += w * (double)d; cc[2]++;
        }
    }
}

// ---------------------------------------------------------------------------
// prep: zero accumulators, row squared norms, bf16 hi/lo split
// ---------------------------------------------------------------------------
__global__ void __launch_bounds__(TPB) prep_kernel(const float* __restrict__ x) {
    if (blockIdx.x == 0 && threadIdx.x < 12) {
        if (threadIdx.x < 8) g_acc[threadIdx.x] = 0.0;
        else                 g_cnt[threadIdx.x - 8] = 0ull;
    }
    int row  = blockIdx.x * (TPB / 32) + (threadIdx.x >> 5);
    int lane = threadIdx.x & 31;
    float4 v = ((const float4*)(x + (size_t)row * DF))[lane];
    float s = v.x * v.x + v.y * v.y + v.z * v.z + v.w * v.w;
#pragma unroll
    for (int o = 16; o; o >>= 1) s += __shfl_xor_sync(0xffffffffu, s, o);
    if (lane == 0) g_sq[row] = s;

    float vv[4] = {v.x, v.y, v.z, v.w};
    __nv_bfloat16 h[4], l[4];
#pragma unroll
    for (int q = 0; q < 4; q++) {
        h[q] = __float2bfloat16(vv[q]);
        l[q] = __float2bfloat16(vv[q] - __bfloat162float(h[q]));
    }
    uint2 ph, pl;
    ph.x = ((uint32_t)__bfloat16_as_ushort(h[1]) << 16) | __bfloat16_as_ushort(h[0]);
    ph.y = ((uint32_t)__bfloat16_as_ushort(h[3]) << 16) | __bfloat16_as_ushort(h[2]);
    pl.x = ((uint32_t)__bfloat16_as_ushort(l[1]) << 16) | __bfloat16_as_ushort(l[0]);
    pl.y = ((uint32_t)__bfloat16_as_ushort(l[3]) << 16) | __bfloat16_as_ushort(l[2]);
    ((uint2*)(g_xh + (size_t)row * DF))[lane] = ph;
    ((uint2*)(g_xl + (size_t)row * DF))[lane] = pl;
}

// ---------------------------------------------------------------------------
// fused tile kernel: HMMA GEMM (bf16 hi/lo) + dist stores + loss
// ---------------------------------------------------------------------------
__global__ void __launch_bounds__(TPB, 1)
dist_loss_kernel(const int* __restrict__ y,
                 const float* __restrict__ mean, const float* __restrict__ stdv,
                 const float* __restrict__ noise, float* __restrict__ out)
{
    const int bi = blockIdx.y, bj = blockIdx.x;
    if (bj < bi) return;
    const int i0 = bi * TILE, j0 = bj * TILE;
    const bool diag = (bi == bj);

    extern __shared__ char smem[];
    __shared__ double sred[8][8];
    __shared__ unsigned scnt[8][4];

    const int tid  = threadIdx.x;
    const int wid  = tid >> 5;
    const int lane = tid & 31;
    const int g    = lane >> 2;       // group id 0..7
    const int tg   = lane & 3;        // thread in group
    const int wm   = wid >> 2;        // warp m-stripe (0/1): rows wm*64..+64
    const int wn   = wid & 3;         // warp n-stripe: cols wn*32..+32

    // panels
    if (tid < 128) {
        ((float*)(smem + OFF_SQJ))[tid] = g_sq[j0 + tid];
        ((int*)(smem + OFF_YJ))[tid]    = y[j0 + tid];
        ((float*)(smem + OFF_SQI))[tid] = g_sq[i0 + tid];
        ((int*)(smem + OFF_YI))[tid]    = y[i0 + tid];
    }

    // load 4 bf16 tiles (row stride 136 bf16 = 17 uint4)
    {
        const __nv_bfloat16* srcs[4] = {g_xh + (size_t)i0 * DF, g_xl + (size_t)i0 * DF,
                                        g_xh + (size_t)j0 * DF, g_xl + (size_t)j0 * DF};
        const uint32_t dsts[4] = {OFF_AH, OFF_AL, OFF_BH, OFF_BL};
#pragma unroll
        for (int t4 = 0; t4 < 4; t4++) {
            const uint4* src = (const uint4*)srcs[t4];
            uint4* dst = (uint4*)(smem + dsts[t4]);
#pragma unroll
            for (int t = 0; t < 8; t++) {
                int idx = tid + t * TPB;              // 0..2047 16B chunks
                int row = idx >> 4, ch = idx & 15;
                dst[row * 17 + ch] = src[row * 16 + ch];
            }
        }
    }
    __syncthreads();

    const uint32_t* Ah = (const uint32_t*)(smem + OFF_AH);
    const uint32_t* Al = (const uint32_t*)(smem + OFF_AL);
    const uint32_t* Bh = (const uint32_t*)(smem + OFF_BH);
    const uint32_t* Bl = (const uint32_t*)(smem + OFF_BL);

    float acc[16][4];
#pragma unroll
    for (int q = 0; q < 16; q++)
#pragma unroll
        for (int e = 0; e < 4; e++) acc[q][e] = 0.f;

    // D = Ah*Bh^T + Ah*Bl^T + Al*Bh^T
#pragma unroll
    for (int pass = 0; pass < 3; pass++) {
        const uint32_t* A = (pass < 2) ? Ah : Al;
        const uint32_t* B = (pass == 1) ? Bl : Bh;
#pragma unroll
        for (int ks = 0; ks < 8; ks++) {
            uint32_t af[4][4], bf[4][2];
#pragma unroll
            for (int mt = 0; mt < 4; mt++) {
                const int r = wm * 64 + mt * 16 + g;
                const uint32_t* ap = A + r * TS + tg + 8 * ks;
                af[mt][0] = ap[0];
                af[mt][1] = ap[8 * TS];
                af[mt][2] = ap[4];
                af[mt][3] = ap[8 * TS + 4];
            }
#pragma unroll
            for (int nt = 0; nt < 4; nt++) {
                const int rb = wn * 32 + nt * 8 + g;
                const uint32_t* bp = B + rb * TS + tg + 8 * ks;
                bf[nt][0] = bp[0];
                bf[nt][1] = bp[4];
            }
#pragma unroll
            for (int mt = 0; mt < 4; mt++)
#pragma unroll
                for (int nt = 0; nt < 4; nt++)
                    mma16816(acc[mt * 4 + nt], af[mt], bf[nt]);
        }
    }
    __syncthreads();   // all warps done reading tiles; staging reuses them

    const float* s_sqj = (const float*)(smem + OFF_SQJ);
    const int*   s_yj  = (const int*)(smem + OFF_YJ);
    const float* s_sqi = (const float*)(smem + OFF_SQI);
    const int*   s_yi  = (const int*)(smem + OFF_YI);
    float* Sd = (float*)(smem + OFF_SD);
    float* St = (float*)(smem + OFF_ST);

    double p[8] = {0, 0, 0, 0, 0, 0, 0, 0};
    unsigned cc4[4] = {0, 0, 0, 0};

#pragma unroll
    for (int mt = 0; mt < 4; mt++) {
        const int r0 = wm * 64 + mt * 16 + g, r1 = r0 + 8;
        const int ia = i0 + r0, ib = i0 + r1;
        const float sqa = s_sqi[r0], sqb = s_sqi[r1];
        const float* mra = mean + (size_t)s_yi[r0] * NC;
        const float* sra = stdv + (size_t)s_yi[r0] * NC;
        const float* mrb = mean + (size_t)s_yi[r1] * NC;
        const float* srb = stdv + (size_t)s_yi[r1] * NC;
        const float* nra = noise + (size_t)ia * Bn;
        const float* nrb = noise + (size_t)ib * Bn;
#pragma unroll
        for (int nt = 0; nt < 4; nt++) {
            const int c = wn * 32 + nt * 8 + 2 * tg;
            const int j = j0 + c;
            const float* a = acc[mt * 4 + nt];
            const float d00 = sqa + s_sqj[c]     - 2.f * a[0];
            const float d01 = sqa + s_sqj[c + 1] - 2.f * a[1];
            const float d10 = sqb + s_sqj[c]     - 2.f * a[2];
            const float d11 = sqb + s_sqj[c + 1] - 2.f * a[3];
            *(float2*)&Sd[r0 * SS + c] = make_float2(d00, d01);
            *(float2*)&Sd[r1 * SS + c] = make_float2(d10, d11);
            if (!diag) {
                St[c * SS + r0] = d00; St[(c + 1) * SS + r0] = d01;
                St[c * SS + r1] = d10; St[(c + 1) * SS + r1] = d11;
            }
            const int yj0 = s_yj[c], yj1 = s_yj[c + 1];
            const float2 na = *(const float2*)(nra + j);
            const float2 nb = *(const float2*)(nrb + j);
            const float cma0 = __ldg(&mra[yj0]), csa0 = __ldg(&sra[yj0]);
            const float cma1 = __ldg(&mra[yj1]), csa1 = __ldg(&sra[yj1]);
            const float cmb0 = __ldg(&mrb[yj0]), csb0 = __ldg(&srb[yj0]);
            const float cmb1 = __ldg(&mrb[yj1]), csb1 = __ldg(&srb[yj1]);
            if (!diag) {          // all pairs negative, all j>i
                neg_term(d00, cma0, csa0, na.x, p, cc4);
                neg_term(d01, cma1, csa1, na.y, p, cc4);
                neg_term(d10, cmb0, csb0, nb.x, p, cc4);
                neg_term(d11, cmb1, csb1, nb.y, p, cc4);
            } else {
                const int gia = ia >> 3, gib = ib >> 3;
#define DIAG_ELEM(jj, dd, cm, cs, nz, ii, gg)                                   \
                if ((jj) > (ii)) {                                              \
                    if (((jj) >> 3) != (gg)) neg_term(dd, cm, cs, nz, p, cc4);  \
                    else {                                                      \
                        const float obs = fmaf(cs, nz, cm);                     \
                        const float tp = obs + 2.0f * cs;                       \
                        if ((dd) > tp) {                                        \
                            p[6] += (double)(dd);                               \
                            p[7] += (double)(dd) * (double)(dd); cc4[3]++;      \
                        }                                                       \
                    }                                                           \
                }
                DIAG_ELEM(j,     d00, cma0, csa0, na.x, ia, gia)
                DIAG_ELEM(j + 1, d01, cma1, csa1, na.y, ia, gia)
                DIAG_ELEM(j,     d10, cmb0, csb0, nb.x, ib, gib)
                DIAG_ELEM(j + 1, d11, cmb1, csb1, nb.y, ib, gib)
#undef DIAG_ELEM
            }
        }
    }
    __syncthreads();

    // coalesced global stores from staging
#pragma unroll
    for (int t = 0; t < 16; t++) {
        const int idx = tid + t * TPB;            // 0..4095 float4 units
        const int r = idx >> 5, c4 = (idx & 31) * 4;
        *(float4*)&out[(size_t)(i0 + r) * Bn + j0 + c4] = *(float4*)&Sd[r * SS + c4];
    }
    if (!diag) {
#pragma unroll
        for (int t = 0; t < 16; t++) {
            const int idx = tid + t * TPB;
            const int jr = idx >> 5, c4 = (idx & 31) * 4;
            *(float4*)&out[(size_t)(j0 + jr) * Bn + i0 + c4] = *(float4*)&St[jr * SS + c4];
        }
    }

    // block reduce + global atomics
#pragma unroll
    for (int q = 0; q < 8; q++) p[q] = wredd(p[q]);
#pragma unroll
    for (int q = 0; q < 4; q++) cc4[q] = wredu(cc4[q]);
    if (lane == 0) {
#pragma unroll
        for (int q = 0; q < 8; q++) sred[wid][q] = p[q];
#pragma unroll
        for (int q = 0; q < 4; q++) scnt[wid][q] = cc4[q];
    }
    __syncthreads();
    if (tid < 8) {
        double s = 0;
#pragma unroll
        for (int w = 0; w < 8; w++) s += sred[w][tid];
        if (s != 0.0) atomicAdd(&g_acc[tid], s);
    } else if (tid < 12) {
        unsigned long long s = 0;
#pragma unroll
        for (int w = 0; w < 8; w++) s += scnt[w][tid - 8];
        if (s) atomicAdd(&g_cnt[tid - 8], s);
    }
}

// ---------------------------------------------------------------------------
__global__ void finalize_kernel(float* __restrict__ out) {
    double l1 = g_cnt[0] ? -(g_acc[1] / (g_acc[0] > 0.0 ? g_acc[0] : 1.0)) : -0.0001;
    double l2 = g_cnt[1] ? -(g_acc[3] / (g_acc[2] > 0.0 ? g_acc[2] : 1.0)) : -0.0001;
    double l3 = g_cnt[2] ? -(g_acc[5] / (g_acc[4] > 0.0 ? g_acc[4] : 1.0)) : -0.0001;
    double lp = g_cnt[3] ?  (g_acc[7] / (g_acc[6] != 0.0 ? g_acc[6] : 1.0)) :  0.0001;
    out[(size_t)Bn * Bn] = (float)(1.0 + (l1 + l2 + l3 + lp) * 0.25);
}

extern "C" void kernel_launch(void* const* d_in, const int* in_sizes, int n_in,
                              void* d_out, int out_size) {
    const float* x     = (const float*)d_in[0];
    const int*   y     = (const int*)d_in[1];
    const float* mean  = (const float*)d_in[2];
    const float* stdv  = (const float*)d_in[3];
    const float* noise = (const float*)d_in[4];
    float* out = (float*)d_out;

    cudaFuncSetAttribute(dist_loss_kernel, cudaFuncAttributeMaxDynamicSharedMemorySize,
                         SMEM_TOTAL);

    prep_kernel<<<Bn / (TPB / 32), TPB>>>(x);
    dim3 grid(Bn / TILE, Bn / TILE);
    dist_loss_kernel<<<grid, TPB, SMEM_TOTAL>>>(y, mean, stdv, noise, out);
    finalize_kernel<<<1, 1>>>(out);
}

// round 9
// speedup vs baseline: 3.5584x; 1.0045x over previous
#include <cuda_runtime.h>
#include <cuda_bf16.h>
#include <math.h>
#include <stdint.h>

#define Bn 4096
#define DF 128
#define NC 512
#define TILE 128
#define TPB 256
#define TS 68           // bf16 tile row stride in 32-bit words (= 136 bf16)
#define SS 132          // f32 staging row stride in words

// smem layout (dynamic)
#define OFF_SQJ 0        // f32[128]
#define OFF_YJ  512      // int[128]
#define OFF_SQI 1024     // f32[128]
#define OFF_YI  1536     // int[128]
#define OFF_AH  2048     // 34816 B each tile (128 rows x 136 bf16)
#define OFF_AL  36864
#define OFF_BH  71680
#define OFF_BL  106496
#define SMEM_TOTAL 141312
#define OFF_SD  OFF_AH   // staging direct: 128 x 132 f32 = 67584 (fits AH+AL)
#define OFF_ST  OFF_BH   // staging transposed: 67584 (fits BH+BL)

// ---------------- device scratch ----------------
__device__ double g_acc[8];
__device__ unsigned long long g_cnt[4];
__device__ float g_sq[Bn];
__device__ __nv_bfloat16 g_xh[Bn * DF];
__device__ __nv_bfloat16 g_xl[Bn * DF];

// bf16 m16n8k16 HMMA (standard PTX, works on plain sm_103 target)
__device__ __forceinline__ void mma16816(float* c, const uint32_t* a, const uint32_t* b) {
    asm volatile(
        "mma.sync.aligned.m16n8k16.row.col.f32.bf16.bf16.f32 "
        "{%0,%1,%2,%3}, {%4,%5,%6,%7}, {%8,%9}, {%0,%1,%2,%3};"
        : "+f"(c[0]), "+f"(c[1]), "+f"(c[2]), "+f"(c[3])
        : "r"(a[0]), "r"(a[1]), "r"(a[2]), "r"(a[3]), "r"(b[0]), "r"(b[1]));
}

// exp(logit), logit in [0, ~250]: fp32 exp2 mantissa * bit-built double scale
__device__ __forceinline__ double fast_exp_pos(float logit) {
    float arg = logit * 1.4426950408889634f;
    float fi = floorf(arg);
    float fr = arg - fi;
    long long e = (long long)(1023 + (int)fi) << 52;
    return __longlong_as_double(e) * (double)exp2f(fr);
}

__device__ __forceinline__ double wredd(double v) {
#pragma unroll
    for (int o = 16; o; o >>= 1) v += __shfl_xor_sync(0xffffffffu, v, o);
    return v;
}
__device__ __forceinline__ unsigned wredu(unsigned v) {
#pragma unroll
    for (int o = 16; o; o >>= 1) v += __shfl_xor_sync(0xffffffffu, v, o);
    return v;
}

// negative-pair loss contribution
__device__ __forceinline__ void neg_term(float d, float cm, float cs, float nz,
                                         double* p, unsigned* cc) {
    const float obs  = fmaf(cs, nz, cm);
    const float tn1  = obs - 2.5f * cs;
    const float tmid = obs - 1.5f * cs;
    if (d < tn1) {
        double w = fast_exp_pos(10.f * (tn1 - d));
        p[0] += w; p[1] += w * (double)d; cc[0]++;
    } else if (d > tn1 && d < tmid) {
        double w = fast_exp_pos(5.f * (tmid - d));
        p[2] += w; p[3] += w * (double)d; cc[1]++;
    } else {
        const float thi = obs + 1.5f * cs;
        if (d > tmid && d < thi) {
            double w = fast_exp_pos(5.f * (thi - d));
            p[4] += w; p[5] += w * (double)d; cc[2]++;
        }
    }
}

// ---------------------------------------------------------------------------
// prep: zero accumulators, row squared norms, bf16 hi/lo split
// ---------------------------------------------------------------------------
__global__ void __launch_bounds__(TPB) prep_kernel(const float* __restrict__ x) {
    if (blockIdx.x == 0 && threadIdx.x < 12) {
        if (threadIdx.x < 8) g_acc[threadIdx.x] = 0.0;
        else                 g_cnt[threadIdx.x - 8] = 0ull;
    }
    int row  = blockIdx.x * (TPB / 32) + (threadIdx.x >> 5);
    int lane = threadIdx.x & 31;
    float4 v = ((const float4*)(x + (size_t)row * DF))[lane];
    float s = v.x * v.x + v.y * v.y + v.z * v.z + v.w * v.w;
#pragma unroll
    for (int o = 16; o; o >>= 1) s += __shfl_xor_sync(0xffffffffu, s, o);
    if (lane == 0) g_sq[row] = s;

    float vv[4] = {v.x, v.y, v.z, v.w};
    __nv_bfloat16 h[4], l[4];
#pragma unroll
    for (int q = 0; q < 4; q++) {
        h[q] = __float2bfloat16(vv[q]);
        l[q] = __float2bfloat16(vv[q] - __bfloat162float(h[q]));
    }
    uint2 ph, pl;
    ph.x = ((uint32_t)__bfloat16_as_ushort(h[1]) << 16) | __bfloat16_as_ushort(h[0]);
    ph.y = ((uint32_t)__bfloat16_as_ushort(h[3]) << 16) | __bfloat16_as_ushort(h[2]);
    pl.x = ((uint32_t)__bfloat16_as_ushort(l[1]) << 16) | __bfloat16_as_ushort(l[0]);
    pl.y = ((uint32_t)__bfloat16_as_ushort(l[3]) << 16) | __bfloat16_as_ushort(l[2]);
    ((uint2*)(g_xh + (size_t)row * DF))[lane] = ph;
    ((uint2*)(g_xl + (size_t)row * DF))[lane] = pl;
}

// ---------------------------------------------------------------------------
// fused tile kernel: HMMA GEMM (bf16 hi/lo) + dist stores + loss
// ---------------------------------------------------------------------------
__global__ void __launch_bounds__(TPB, 1)
dist_loss_kernel(const int* __restrict__ y,
                 const float* __restrict__ mean, const float* __restrict__ stdv,
                 const float* __restrict__ noise, float* __restrict__ out)
{
    const int bi = blockIdx.y, bj = blockIdx.x;
    if (bj < bi) return;
    const int i0 = bi * TILE, j0 = bj * TILE;
    const bool diag = (bi == bj);

    extern __shared__ char smem[];
    __shared__ double sred[8][8];
    __shared__ unsigned scnt[8][4];

    const int tid  = threadIdx.x;
    const int wid  = tid >> 5;
    const int lane = tid & 31;
    const int g    = lane >> 2;       // group id 0..7
    const int tg   = lane & 3;        // thread in group
    const int wm   = wid >> 2;        // warp m-stripe (0/1): rows wm*64..+64
    const int wn   = wid & 3;         // warp n-stripe: cols wn*32..+32

    // panels
    if (tid < 128) {
        ((float*)(smem + OFF_SQJ))[tid] = g_sq[j0 + tid];
        ((int*)(smem + OFF_YJ))[tid]    = y[j0 + tid];
        ((float*)(smem + OFF_SQI))[tid] = g_sq[i0 + tid];
        ((int*)(smem + OFF_YI))[tid]    = y[i0 + tid];
    }

    // load 4 bf16 tiles (row stride 136 bf16 = 17 uint4)
    {
        const __nv_bfloat16* srcs[4] = {g_xh + (size_t)i0 * DF, g_xl + (size_t)i0 * DF,
                                        g_xh + (size_t)j0 * DF, g_xl + (size_t)j0 * DF};
        const uint32_t dsts[4] = {OFF_AH, OFF_AL, OFF_BH, OFF_BL};
#pragma unroll
        for (int t4 = 0; t4 < 4; t4++) {
            const uint4* src = (const uint4*)srcs[t4];
            uint4* dst = (uint4*)(smem + dsts[t4]);
#pragma unroll
            for (int t = 0; t < 8; t++) {
                int idx = tid + t * TPB;              // 0..2047 16B chunks
                int row = idx >> 4, ch = idx & 15;
                dst[row * 17 + ch] = src[row * 16 + ch];
            }
        }
    }
    __syncthreads();

    const uint32_t* Ah = (const uint32_t*)(smem + OFF_AH);
    const uint32_t* Al = (const uint32_t*)(smem + OFF_AL);
    const uint32_t* Bh = (const uint32_t*)(smem + OFF_BH);
    const uint32_t* Bl = (const uint32_t*)(smem + OFF_BL);

    float acc[16][4];
#pragma unroll
    for (int q = 0; q < 16; q++)
#pragma unroll
        for (int e = 0; e < 4; e++) acc[q][e] = 0.f;

    // D = Ah*Bh^T + Ah*Bl^T + Al*Bh^T
#pragma unroll
    for (int pass = 0; pass < 3; pass++) {
        const uint32_t* A = (pass < 2) ? Ah : Al;
        const uint32_t* B = (pass == 1) ? Bl : Bh;
#pragma unroll
        for (int ks = 0; ks < 8; ks++) {
            uint32_t af[4][4], bf[4][2];
#pragma unroll
            for (int mt = 0; mt < 4; mt++) {
                const int r = wm * 64 + mt * 16 + g;
                const uint32_t* ap = A + r * TS + tg + 8 * ks;
                af[mt][0] = ap[0];
                af[mt][1] = ap[8 * TS];
                af[mt][2] = ap[4];
                af[mt][3] = ap[8 * TS + 4];
            }
#pragma unroll
            for (int nt = 0; nt < 4; nt++) {
                const int rb = wn * 32 + nt * 8 + g;
                const uint32_t* bp = B + rb * TS + tg + 8 * ks;
                bf[nt][0] = bp[0];
                bf[nt][1] = bp[4];
            }
#pragma unroll
            for (int mt = 0; mt < 4; mt++)
#pragma unroll
                for (int nt = 0; nt < 4; nt++)
                    mma16816(acc[mt * 4 + nt], af[mt], bf[nt]);
        }
    }
    __syncthreads();   // all warps done reading tiles; staging reuses them

    const float* s_sqj = (const float*)(smem + OFF_SQJ);
    const int*   s_yj  = (const int*)(smem + OFF_YJ);
    const float* s_sqi = (const float*)(smem + OFF_SQI);
    const int*   s_yi  = (const int*)(smem + OFF_YI);
    float* Sd = (float*)(smem + OFF_SD);
    float* St = (float*)(smem + OFF_ST);

    double p[8] = {0, 0, 0, 0, 0, 0, 0, 0};
    unsigned cc4[4] = {0, 0, 0, 0};

#pragma unroll
    for (int mt = 0; mt < 4; mt++) {
        const int r0 = wm * 64 + mt * 16 + g, r1 = r0 + 8;
        const int ia = i0 + r0, ib = i0 + r1;
        const float sqa = s_sqi[r0], sqb = s_sqi[r1];
        const float* mra = mean + (size_t)s_yi[r0] * NC;
        const float* sra = stdv + (size_t)s_yi[r0] * NC;
        const float* mrb = mean + (size_t)s_yi[r1] * NC;
        const float* srb = stdv + (size_t)s_yi[r1] * NC;
        const float* nra = noise + (size_t)ia * Bn;
        const float* nrb = noise + (size_t)ib * Bn;
#pragma unroll
        for (int nt = 0; nt < 4; nt++) {
            const int c = wn * 32 + nt * 8 + 2 * tg;
            const int j = j0 + c;
            const float* a = acc[mt * 4 + nt];
            const float d00 = sqa + s_sqj[c]     - 2.f * a[0];
            const float d01 = sqa + s_sqj[c + 1] - 2.f * a[1];
            const float d10 = sqb + s_sqj[c]     - 2.f * a[2];
            const float d11 = sqb + s_sqj[c + 1] - 2.f * a[3];
            *(float2*)&Sd[r0 * SS + c] = make_float2(d00, d01);
            *(float2*)&Sd[r1 * SS + c] = make_float2(d10, d11);
            if (!diag) {
                St[c * SS + r0] = d00; St[(c + 1) * SS + r0] = d01;
                St[c * SS + r1] = d10; St[(c + 1) * SS + r1] = d11;
            }
            const int yj0 = s_yj[c], yj1 = s_yj[c + 1];
            const float2 na = *(const float2*)(nra + j);
            const float2 nb = *(const float2*)(nrb + j);
            const float cma0 = __ldg(&mra[yj0]), csa0 = __ldg(&sra[yj0]);
            const float cma1 = __ldg(&mra[yj1]), csa1 = __ldg(&sra[yj1]);
            const float cmb0 = __ldg(&mrb[yj0]), csb0 = __ldg(&srb[yj0]);
            const float cmb1 = __ldg(&mrb[yj1]), csb1 = __ldg(&srb[yj1]);
            if (!diag) {          // all pairs negative, all j>i
                neg_term(d00, cma0, csa0, na.x, p, cc4);
                neg_term(d01, cma1, csa1, na.y, p, cc4);
                neg_term(d10, cmb0, csb0, nb.x, p, cc4);
                neg_term(d11, cmb1, csb1, nb.y, p, cc4);
            } else {
                const int gia = ia >> 3, gib = ib >> 3;
#define DIAG_ELEM(jj, dd, cm, cs, nz, ii, gg)                                   \
                if ((jj) > (ii)) {                                              \
                    if (((jj) >> 3) != (gg)) neg_term(dd, cm, cs, nz, p, cc4);  \
                    else {                                                      \
                        const float obs = fmaf(cs, nz, cm);                     \
                        const float tp = obs + 2.0f * cs;                       \
                        if ((dd) > tp) {                                        \
                            p[6] += (double)(dd);                               \
                            p[7] += (double)(dd) * (double)(dd); cc4[3]++;      \
                        }                                                       \
                    }                                                           \
                }
                DIAG_ELEM(j,     d00, cma0, csa0, na.x, ia, gia)
                DIAG_ELEM(j + 1, d01, cma1, csa1, na.y, ia, gia)
                DIAG_ELEM(j,     d10, cmb0, csb0, nb.x, ib, gib)
                DIAG_ELEM(j + 1, d11, cmb1, csb1, nb.y, ib, gib)
#undef DIAG_ELEM
            }
        }
    }
    __syncthreads();

    // coalesced global stores from staging
#pragma unroll
    for (int t = 0; t < 16; t++) {
        const int idx = tid + t * TPB;            // 0..4095 float4 units
        const int r = idx >> 5, c4 = (idx & 31) * 4;
        *(float4*)&out[(size_t)(i0 + r) * Bn + j0 + c4] = *(float4*)&Sd[r * SS + c4];
    }
    if (!diag) {
#pragma unroll
        for (int t = 0; t < 16; t++) {
            const int idx = tid + t * TPB;
            const int jr = idx >> 5, c4 = (idx & 31) * 4;
            *(float4*)&out[(size_t)(j0 + jr) * Bn + i0 + c4] = *(float4*)&St[jr * SS + c4];
        }
    }

    // block reduce + global atomics
#pragma unroll
    for (int q = 0; q < 8; q++) p[q] = wredd(p[q]);
#pragma unroll
    for (int q = 0; q < 4; q++) cc4[q] = wredu(cc4[q]);
    if (lane == 0) {
#pragma unroll
        for (int q = 0; q < 8; q++) sred[wid][q] = p[q];
#pragma unroll
        for (int q = 0; q < 4; q++) scnt[wid][q] = cc4[q];
    }
    __syncthreads();
    if (tid < 8) {
        double s = 0;
#pragma unroll
        for (int w = 0; w < 8; w++) s += sred[w][tid];
        if (s != 0.0) atomicAdd(&g_acc[tid], s);
    } else if (tid < 12) {
        unsigned long long s = 0;
#pragma unroll
        for (int w = 0; w < 8; w++) s += scnt[w][tid - 8];
        if (s) atomicAdd(&g_cnt[tid - 8], s);
    }
}

// ---------------------------------------------------------------------------
__global__ void finalize_kernel(float* __restrict__ out) {
    double l1 = g_cnt[0] ? -(g_acc[1] / (g_acc[0] > 0.0 ? g_acc[0] : 1.0)) : -0.0001;
    double l2 = g_cnt[1] ? -(g_acc[3] / (g_acc[2] > 0.0 ? g_acc[2] : 1.0)) : -0.0001;
    double l3 = g_cnt[2] ? -(g_acc[5] / (g_acc[4] > 0.0 ? g_acc[4] : 1.0)) : -0.0001;
    double lp = g_cnt[3] ?  (g_acc[7] / (g_acc[6] != 0.0 ? g_acc[6] : 1.0)) :  0.0001;
    out[(size_t)Bn * Bn] = (float)(1.0 + (l1 + l2 + l3 + lp) * 0.25);
}

extern "C" void kernel_launch(void* const* d_in, const int* in_sizes, int n_in,
                              void* d_out, int out_size) {
    const float* x     = (const float*)d_in[0];
    const int*   y     = (const int*)d_in[1];
    const float* mean  = (const float*)d_in[2];
    const float* stdv  = (const float*)d_in[3];
    const float* noise = (const float*)d_in[4];
    float* out = (float*)d_out;

    cudaFuncSetAttribute(dist_loss_kernel, cudaFuncAttributeMaxDynamicSharedMemorySize,
                         SMEM_TOTAL);

    prep_kernel<<<Bn / (TPB / 32), TPB>>>(x);
    dim3 grid(Bn / TILE, Bn / TILE);
    dist_loss_kernel<<<grid, TPB, SMEM_TOTAL>>>(y, mean, stdv, noise, out);
    finalize_kernel<<<1, 1>>>(out);
}